// round 1
// baseline (speedup 1.0000x reference)
#include <cuda_runtime.h>
#include <stdint.h>

// ---------------- problem constants ----------------
constexpr int N  = 50000;
constexpr int E  = 800000;
constexpr int NG = 128;
constexpr int D  = 128;
constexpr int M  = 2;
constexpr int NT = 10;

// ---------------- device scratch (static, allowed) ----------------
__device__ float g_tx[N * D];          // encoded node features
__device__ float g_bufA[M * N * D];    // ping
__device__ float g_bufB[M * N * D];    // pong
__device__ int   g_deg[N];
__device__ int   g_rowoff[N + 1];
__device__ int   g_cursor[N];
__device__ int   g_csrsrc[E];
__device__ int   g_gstart[NG + 1];
__device__ float g_pred[N];
__device__ float g_gmax[NG];
__device__ float g_gsum[NG];
__device__ int   g_anchor[M * NG];
__device__ float g_hg[M * NG * D];

// ---------------- threefry2x32 (exact JAX) ----------------
__device__ __forceinline__ uint2 threefry2x32(unsigned k0, unsigned k1,
                                              unsigned x0, unsigned x1) {
  unsigned k2 = k0 ^ k1 ^ 0x1BD11BDAu;
  x0 += k0; x1 += k1;
#define TF_ROT(x, d) (((x) << (d)) | ((x) >> (32 - (d))))
#define TF_RND(r) { x0 += x1; x1 = TF_ROT(x1, r); x1 ^= x0; }
  TF_RND(13) TF_RND(15) TF_RND(26) TF_RND(6)
  x0 += k1; x1 += k2 + 1u;
  TF_RND(17) TF_RND(29) TF_RND(16) TF_RND(24)
  x0 += k2; x1 += k0 + 2u;
  TF_RND(13) TF_RND(15) TF_RND(26) TF_RND(6)
  x0 += k0; x1 += k1 + 3u;
  TF_RND(17) TF_RND(29) TF_RND(16) TF_RND(24)
  x0 += k1; x1 += k2 + 4u;
  TF_RND(13) TF_RND(15) TF_RND(26) TF_RND(6)
  x0 += k2; x1 += k0 + 5u;
#undef TF_RND
#undef TF_ROT
  return make_uint2(x0, x1);
}

// ---------------- kernels ----------------

// embed rows + zero deg + graph boundaries (batch is sorted)
__global__ void k_embed(const int* __restrict__ x_idx,
                        const int* __restrict__ batch,
                        const float* __restrict__ x_table) {
  int n = blockIdx.x;
  int d = threadIdx.x;
  g_tx[n * D + d] = x_table[x_idx[n] * D + d];
  if (d == 0) {
    g_deg[n] = 0;
    int b = batch[n];
    if (n == 0) {
      for (int g = 0; g <= b; ++g) g_gstart[g] = 0;
    } else {
      int pb = batch[n - 1];
      for (int g = pb + 1; g <= b; ++g) g_gstart[g] = n;
    }
    if (n == N - 1) {
      for (int g = b + 1; g <= NG; ++g) g_gstart[g] = N;
    }
  }
}

__global__ void k_hist(const int* __restrict__ edge_dst) {
  int e = blockIdx.x * blockDim.x + threadIdx.x;
  if (e < E) atomicAdd(&g_deg[edge_dst[e]], 1);
}

// single-block exclusive scan of deg -> rowoff (+cursor copy)
__global__ void k_scan() {
  __shared__ int sums[1024];
  int tid = threadIdx.x;
  const int CH = (N + 1023) / 1024;
  int beg = tid * CH;
  int end = min(beg + CH, N);
  int s = 0;
  for (int i = beg; i < end; ++i) s += g_deg[i];
  sums[tid] = s;
  __syncthreads();
  for (int off = 1; off < 1024; off <<= 1) {
    int v = (tid >= off) ? sums[tid - off] : 0;
    __syncthreads();
    sums[tid] += v;
    __syncthreads();
  }
  int pre = (tid == 0) ? 0 : sums[tid - 1];
  for (int i = beg; i < end; ++i) {
    g_rowoff[i] = pre;
    g_cursor[i] = pre;
    pre += g_deg[i];
  }
  if (tid == 1023) g_rowoff[N] = sums[1023];
}

__global__ void k_scatter(const int* __restrict__ edge_src,
                          const int* __restrict__ edge_dst) {
  int e = blockIdx.x * blockDim.x + threadIdx.x;
  if (e < E) {
    int d = edge_dst[e];
    int pos = atomicAdd(&g_cursor[d], 1);
    g_csrsrc[pos] = edge_src[e];
  }
}

// z[m,n,:] = h[m,n,:] + sum_{e: dst==n} h[m,src,:]   (one warp per node)
template <int MM>
__global__ void __launch_bounds__(256) k_agg(const float* __restrict__ hin,
                                             float* __restrict__ zout) {
  int w = (blockIdx.x * blockDim.x + threadIdx.x) >> 5;
  int lane = threadIdx.x & 31;
  if (w >= N) return;
  int beg = g_rowoff[w], end = g_rowoff[w + 1];
  float4 acc[MM];
#pragma unroll
  for (int m = 0; m < MM; ++m)
    acc[m] = *reinterpret_cast<const float4*>(hin + (m * N + w) * D + lane * 4);
  int k = beg;
  for (; k + 1 < end; k += 2) {
    int s0 = g_csrsrc[k];
    int s1 = g_csrsrc[k + 1];
#pragma unroll
    for (int m = 0; m < MM; ++m) {
      float4 v0 = *reinterpret_cast<const float4*>(hin + (m * N + s0) * D + lane * 4);
      float4 v1 = *reinterpret_cast<const float4*>(hin + (m * N + s1) * D + lane * 4);
      acc[m].x += v0.x + v1.x; acc[m].y += v0.y + v1.y;
      acc[m].z += v0.z + v1.z; acc[m].w += v0.w + v1.w;
    }
  }
  if (k < end) {
    int s0 = g_csrsrc[k];
#pragma unroll
    for (int m = 0; m < MM; ++m) {
      float4 v0 = *reinterpret_cast<const float4*>(hin + (m * N + s0) * D + lane * 4);
      acc[m].x += v0.x; acc[m].y += v0.y; acc[m].z += v0.z; acc[m].w += v0.w;
    }
  }
#pragma unroll
  for (int m = 0; m < MM; ++m)
    *reinterpret_cast<float4*>(zout + (m * N + w) * D + lane * 4) = acc[m];
}

// out[r,:] = act(Z[r,:] @ W + bias) ; W is [128,128] row-major, BN = full 128
__global__ void __launch_bounds__(256) k_gemm128(int R, const float* __restrict__ Z,
                                                 const float* __restrict__ W,
                                                 const float* __restrict__ bias,
                                                 float* __restrict__ out,
                                                 int doRelu) {
  __shared__ float Zs[16][64 + 4];  // [BK][BM+pad], pad keeps float4 alignment (68*4 = 272 = 17*16)
  __shared__ float Ws[16][128];
  int row0 = blockIdx.x * 64;
  int tid = threadIdx.x;
  int tr = tid >> 4;        // 0..15 -> rows tr*4..tr*4+3
  int tc = tid & 15;        // 0..15 -> cols tc*8..tc*8+7
  int zr = tid >> 2;        // 0..63
  int zk = (tid & 3) * 4;   // 0,4,8,12
  int wk = tid >> 4;        // 0..15
  int wj = (tid & 15) * 8;  // 0..120
  float acc[4][8] = {};
  for (int k0 = 0; k0 < 128; k0 += 16) {
    float4 zv = make_float4(0.f, 0.f, 0.f, 0.f);
    int gr = row0 + zr;
    if (gr < R) zv = *reinterpret_cast<const float4*>(Z + (size_t)gr * 128 + k0 + zk);
    Zs[zk + 0][zr] = zv.x; Zs[zk + 1][zr] = zv.y;
    Zs[zk + 2][zr] = zv.z; Zs[zk + 3][zr] = zv.w;
    float4 w0 = *reinterpret_cast<const float4*>(W + (size_t)(k0 + wk) * 128 + wj);
    float4 w1 = *reinterpret_cast<const float4*>(W + (size_t)(k0 + wk) * 128 + wj + 4);
    *reinterpret_cast<float4*>(&Ws[wk][wj]) = w0;
    *reinterpret_cast<float4*>(&Ws[wk][wj + 4]) = w1;
    __syncthreads();
#pragma unroll
    for (int kk = 0; kk < 16; ++kk) {
      float4 z4 = *reinterpret_cast<const float4*>(&Zs[kk][tr * 4]);
      float4 wA = *reinterpret_cast<const float4*>(&Ws[kk][tc * 8]);
      float4 wB = *reinterpret_cast<const float4*>(&Ws[kk][tc * 8 + 4]);
      float zr4[4] = {z4.x, z4.y, z4.z, z4.w};
      float wr[8]  = {wA.x, wA.y, wA.z, wA.w, wB.x, wB.y, wB.z, wB.w};
#pragma unroll
      for (int i = 0; i < 4; ++i)
#pragma unroll
        for (int j = 0; j < 8; ++j)
          acc[i][j] += zr4[i] * wr[j];
    }
    __syncthreads();
  }
#pragma unroll
  for (int i = 0; i < 4; ++i) {
    int r = row0 + tr * 4 + i;
    if (r < R) {
      float4 o0, o1;
      o0.x = acc[i][0] + bias[tc * 8 + 0]; o0.y = acc[i][1] + bias[tc * 8 + 1];
      o0.z = acc[i][2] + bias[tc * 8 + 2]; o0.w = acc[i][3] + bias[tc * 8 + 3];
      o1.x = acc[i][4] + bias[tc * 8 + 4]; o1.y = acc[i][5] + bias[tc * 8 + 5];
      o1.z = acc[i][6] + bias[tc * 8 + 6]; o1.w = acc[i][7] + bias[tc * 8 + 7];
      if (doRelu) {
        o0.x = fmaxf(o0.x, 0.f); o0.y = fmaxf(o0.y, 0.f);
        o0.z = fmaxf(o0.z, 0.f); o0.w = fmaxf(o0.w, 0.f);
        o1.x = fmaxf(o1.x, 0.f); o1.y = fmaxf(o1.y, 0.f);
        o1.z = fmaxf(o1.z, 0.f); o1.w = fmaxf(o1.w, 0.f);
      }
      *reinterpret_cast<float4*>(out + (size_t)r * 128 + tc * 8) = o0;
      *reinterpret_cast<float4*>(out + (size_t)r * 128 + tc * 8 + 4) = o1;
    }
  }
}

// pred[n] = h[n,:] . Wd + bd  (one warp per node)
__global__ void k_pred(const float* __restrict__ h, const float* __restrict__ Wd,
                       const float* __restrict__ bd) {
  int w = (blockIdx.x * blockDim.x + threadIdx.x) >> 5;
  int lane = threadIdx.x & 31;
  if (w >= N) return;
  float4 hv = *reinterpret_cast<const float4*>(h + w * D + lane * 4);
  float4 wv = *reinterpret_cast<const float4*>(Wd + lane * 4);
  float s = hv.x * wv.x + hv.y * wv.y + hv.z * wv.z + hv.w * wv.w;
#pragma unroll
  for (int off = 16; off; off >>= 1) s += __shfl_xor_sync(0xffffffffu, s, off);
  if (lane == 0) g_pred[w] = s + bd[0];
}

// per-graph softmax stats (max + sum of exp)
__global__ void k_gstats() {
  int g = blockIdx.x;
  int tid = threadIdx.x;
  int beg = g_gstart[g], end = g_gstart[g + 1];
  __shared__ float red[256];
  float mx = -3.4e38f;
  for (int n = beg + tid; n < end; n += 256) mx = fmaxf(mx, g_pred[n]);
  red[tid] = mx;
  __syncthreads();
  for (int off = 128; off; off >>= 1) {
    if (tid < off) red[tid] = fmaxf(red[tid], red[tid + off]);
    __syncthreads();
  }
  float mxv = red[0];
  __syncthreads();
  float s = 0.f;
  for (int n = beg + tid; n < end; n += 256) s += expf(g_pred[n] - mxv);
  red[tid] = s;
  __syncthreads();
  for (int off = 128; off; off >>= 1) {
    if (tid < off) red[tid] += red[tid + off];
    __syncthreads();
  }
  if (tid == 0) {
    bool ok = beg < end;
    g_gmax[g] = ok ? mxv : 0.f;
    g_gsum[g] = ok ? red[0] : 1.f;
  }
}

// Gumbel-max sampling: one block per (m, graph)
__global__ void k_sample() {
  int b = blockIdx.x;           // b = m*NG + g
  int m = b >> 7;
  int g = b & 127;
  int tid = threadIdx.x;
  int beg = g_gstart[g], end = g_gstart[g + 1];
  if (beg >= end) {
    if (tid == 0) g_anchor[b] = -1;
    return;
  }
  uint2 dk = threefry2x32(0u, 1u, 0u, 1u);  // fold_in(key(1), 1)
  float mxv = g_gmax[g];
  float sv = g_gsum[g];
  float best = -3.4e38f;
  int bid = 0x7fffffff;
  for (int n = beg + tid; n < end; n += 128) {
    float prob = expf(g_pred[n] - mxv) / sv;
    float lp = logf(prob + 1e-15f);
    uint2 r = threefry2x32(dk.x, dk.y, (unsigned)n, (unsigned)(N + n));
    unsigned bits = (m == 0) ? r.x : r.y;
    float u = __uint_as_float((bits >> 9) | 0x3f800000u) - 1.0f;
    float gum = -logf(-logf(u + 1e-12f) + 1e-12f);
    float sc = lp + gum;
    if (sc > best || (sc == best && n < bid)) { best = sc; bid = n; }
  }
  __shared__ float rs[128];
  __shared__ int ri[128];
  rs[tid] = best; ri[tid] = bid;
  __syncthreads();
  for (int off = 64; off; off >>= 1) {
    if (tid < off) {
      if (rs[tid + off] > rs[tid] ||
          (rs[tid + off] == rs[tid] && ri[tid + off] < ri[tid])) {
        rs[tid] = rs[tid + off];
        ri[tid] = ri[tid + off];
      }
    }
    __syncthreads();
  }
  if (tid == 0) g_anchor[b] = ri[0];
}

// bufA[m] = tx (both m)
__global__ void k_copyx() {
  int i = blockIdx.x * blockDim.x + threadIdx.x;
  if (i < N * D) {
    float v = g_tx[i];
    g_bufA[i] = v;
    g_bufA[N * D + i] = v;
  }
}

// apply anchor modulation at sampled nodes: x = tx * (1 + at[1])
__global__ void k_anchor_apply(const float* __restrict__ anchor_table) {
  int b = blockIdx.x;  // m*NG+g
  int d = threadIdx.x;
  int n = g_anchor[b];
  if (n < 0) return;
  int m = b >> 7;
  float f = 1.0f + anchor_table[D + d];
  g_bufA[(m * N + n) * D + d] = g_tx[n * D + d] * f;
}

// mean pool per (m, graph)
__global__ void k_pool(const float* __restrict__ hn) {
  int b = blockIdx.x;  // m*NG+g
  int m = b >> 7;
  int g = b & 127;
  int d = threadIdx.x;
  int beg = g_gstart[g], end = g_gstart[g + 1];
  float acc = 0.f;
  for (int n = beg; n < end; ++n) acc += hn[(m * N + n) * D + d];
  int c = end - beg;
  float inv = 1.0f / (float)max(c, 1);
  g_hg[b * D + d] = acc * inv;
}

// out[g,t] = mean_m(hg[m,g] @ Wp + bp)
__global__ void k_out(const float* __restrict__ Wp, const float* __restrict__ bp,
                      float* __restrict__ out) {
  int g = blockIdx.x;
  int t = threadIdx.x;
  if (t >= NT) return;
  float acc = 0.f;
  for (int m = 0; m < M; ++m) {
    const float* hg = &g_hg[(m * NG + g) * D];
    float s = 0.f;
#pragma unroll 16
    for (int k = 0; k < D; ++k) s += hg[k] * Wp[k * NT + t];
    acc += s;
  }
  out[g * NT + t] = acc * (1.0f / M) + bp[t];
}

// ---------------- launch ----------------
extern "C" void kernel_launch(void* const* d_in, const int* in_sizes, int n_in,
                              void* d_out, int out_size) {
  const int*   x_idx    = (const int*)d_in[0];
  const int*   edge_src = (const int*)d_in[1];
  const int*   edge_dst = (const int*)d_in[2];
  const int*   batch    = (const int*)d_in[3];
  const float* x_table  = (const float*)d_in[4];
  const float* anchor_t = (const float*)d_in[5];
  const float* Wg       = (const float*)d_in[6];
  const float* bg       = (const float*)d_in[7];
  const float* Wn       = (const float*)d_in[8];
  const float* bn       = (const float*)d_in[9];
  const float* Wd       = (const float*)d_in[10];
  const float* bd       = (const float*)d_in[11];
  const float* Wp       = (const float*)d_in[12];
  const float* bp       = (const float*)d_in[13];
  float* out = (float*)d_out;

  float *txp, *bufA, *bufB;
  cudaGetSymbolAddress((void**)&txp, g_tx);
  cudaGetSymbolAddress((void**)&bufA, g_bufA);
  cudaGetSymbolAddress((void**)&bufB, g_bufB);

  const int AGG_GRID = (N * 32 + 255) / 256;        // one warp per node
  const int GEMM1 = (N + 63) / 64;                  // 50000 rows
  const int GEMM2 = (M * N + 63) / 64;              // 100000 rows

  // ---- prep: embed + CSR(dst) build ----
  k_embed<<<N, D>>>(x_idx, batch, x_table);
  k_hist<<<(E + 255) / 256, 256>>>(edge_dst);
  k_scan<<<1, 1024>>>();
  k_scatter<<<(E + 255) / 256, 256>>>(edge_src, edge_dst);

  // ---- GNN pass 1 (M collapsed to 1) ----
  k_agg<1><<<AGG_GRID, 256>>>(txp, bufB);
  k_gemm128<<<GEMM1, 256>>>(N, bufB, Wg, bg, bufA, 1);
  k_agg<1><<<AGG_GRID, 256>>>(bufA, bufB);
  k_gemm128<<<GEMM1, 256>>>(N, bufB, Wg + D * D, bg + D, bufA, 1);

  // ---- distance head + per-graph softmax + Gumbel-max sample ----
  k_pred<<<AGG_GRID, 256>>>(bufA, Wd, bd);
  k_gstats<<<NG, 256>>>();
  k_sample<<<M * NG, 128>>>();

  // ---- anchored re-embed ----
  k_copyx<<<(N * D + 255) / 256, 256>>>();
  k_anchor_apply<<<M * NG, D>>>(anchor_t);

  // ---- GNN pass 2 (M = 2) ----
  k_agg<2><<<AGG_GRID, 256>>>(bufA, bufB);
  k_gemm128<<<GEMM2, 256>>>(M * N, bufB, Wg, bg, bufA, 1);
  k_agg<2><<<AGG_GRID, 256>>>(bufA, bufB);
  k_gemm128<<<GEMM2, 256>>>(M * N, bufB, Wg + D * D, bg + D, bufA, 1);

  // ---- node MLP + pool + task head ----
  k_gemm128<<<GEMM2, 256>>>(M * N, bufA, Wn, bn, bufB, 1);
  k_pool<<<M * NG, D>>>(bufB);
  k_out<<<NG, 32>>>(Wp, bp, out);
}

// round 2
// speedup vs baseline: 1.0330x; 1.0330x over previous
#include <cuda_runtime.h>
#include <stdint.h>

// ---------------- problem constants ----------------
constexpr int N  = 50000;
constexpr int E  = 800000;
constexpr int NG = 128;
constexpr int D  = 128;
constexpr int M  = 2;
constexpr int NT = 10;

typedef unsigned long long ull;

// ---------------- device scratch (static, allowed) ----------------
__device__ float g_tx[N * D];          // encoded node features
__device__ float g_bufA[M * N * D];    // ping
__device__ float g_bufB[M * N * D];    // pong
__device__ int   g_deg[N];
__device__ int   g_rowoff[N + 1];
__device__ int   g_cursor[N];
__device__ int   g_csrsrc[E];
__device__ int   g_gstart[NG + 1];
__device__ float g_pred[N];
__device__ float g_gmax[NG];
__device__ float g_gsum[NG];
__device__ int   g_anchor[M * NG];
__device__ float g_hg[M * NG * D];

// ---------------- f32x2 packed math helpers ----------------
__device__ __forceinline__ ull ffma2(ull a, ull b, ull c) {
  ull d;
  asm("fma.rn.f32x2 %0, %1, %2, %3;" : "=l"(d) : "l"(a), "l"(b), "l"(c));
  return d;
}
__device__ __forceinline__ ull pack2dup(float x) {
  ull r;
  asm("mov.b64 %0, {%1, %1};" : "=l"(r) : "f"(x));
  return r;
}
__device__ __forceinline__ void unpack2(ull v, float& lo, float& hi) {
  asm("mov.b64 {%0, %1}, %2;" : "=f"(lo), "=f"(hi) : "l"(v));
}

// ---------------- threefry2x32 (exact JAX) ----------------
__device__ __forceinline__ uint2 threefry2x32(unsigned k0, unsigned k1,
                                              unsigned x0, unsigned x1) {
  unsigned k2 = k0 ^ k1 ^ 0x1BD11BDAu;
  x0 += k0; x1 += k1;
#define TF_ROT(x, d) (((x) << (d)) | ((x) >> (32 - (d))))
#define TF_RND(r) { x0 += x1; x1 = TF_ROT(x1, r); x1 ^= x0; }
  TF_RND(13) TF_RND(15) TF_RND(26) TF_RND(6)
  x0 += k1; x1 += k2 + 1u;
  TF_RND(17) TF_RND(29) TF_RND(16) TF_RND(24)
  x0 += k2; x1 += k0 + 2u;
  TF_RND(13) TF_RND(15) TF_RND(26) TF_RND(6)
  x0 += k0; x1 += k1 + 3u;
  TF_RND(17) TF_RND(29) TF_RND(16) TF_RND(24)
  x0 += k1; x1 += k2 + 4u;
  TF_RND(13) TF_RND(15) TF_RND(26) TF_RND(6)
  x0 += k2; x1 += k0 + 5u;
#undef TF_RND
#undef TF_ROT
  return make_uint2(x0, x1);
}

// ---------------- kernels ----------------

// embed rows + zero deg + graph boundaries (batch is sorted)
__global__ void k_embed(const int* __restrict__ x_idx,
                        const int* __restrict__ batch,
                        const float* __restrict__ x_table) {
  int n = blockIdx.x;
  int d = threadIdx.x;
  g_tx[n * D + d] = x_table[x_idx[n] * D + d];
  if (d == 0) {
    g_deg[n] = 0;
    int b = batch[n];
    if (n == 0) {
      for (int g = 0; g <= b; ++g) g_gstart[g] = 0;
    } else {
      int pb = batch[n - 1];
      for (int g = pb + 1; g <= b; ++g) g_gstart[g] = n;
    }
    if (n == N - 1) {
      for (int g = b + 1; g <= NG; ++g) g_gstart[g] = N;
    }
  }
}

__global__ void k_hist(const int* __restrict__ edge_dst) {
  int e = blockIdx.x * blockDim.x + threadIdx.x;
  if (e < E) atomicAdd(&g_deg[edge_dst[e]], 1);
}

// single-block exclusive scan of deg -> rowoff (+cursor copy)
__global__ void k_scan() {
  __shared__ int sums[1024];
  int tid = threadIdx.x;
  const int CH = (N + 1023) / 1024;
  int beg = tid * CH;
  int end = min(beg + CH, N);
  int s = 0;
  for (int i = beg; i < end; ++i) s += g_deg[i];
  sums[tid] = s;
  __syncthreads();
  for (int off = 1; off < 1024; off <<= 1) {
    int v = (tid >= off) ? sums[tid - off] : 0;
    __syncthreads();
    sums[tid] += v;
    __syncthreads();
  }
  int pre = (tid == 0) ? 0 : sums[tid - 1];
  for (int i = beg; i < end; ++i) {
    g_rowoff[i] = pre;
    g_cursor[i] = pre;
    pre += g_deg[i];
  }
  if (tid == 1023) g_rowoff[N] = sums[1023];
}

__global__ void k_scatter(const int* __restrict__ edge_src,
                          const int* __restrict__ edge_dst) {
  int e = blockIdx.x * blockDim.x + threadIdx.x;
  if (e < E) {
    int d = edge_dst[e];
    int pos = atomicAdd(&g_cursor[d], 1);
    g_csrsrc[pos] = edge_src[e];
  }
}

// z[m,n,:] = h[m,n,:] + sum_{e: dst==n} h[m,src,:]   (one warp per node)
template <int MM>
__global__ void __launch_bounds__(256) k_agg(const float* __restrict__ hin,
                                             float* __restrict__ zout) {
  int w = (blockIdx.x * blockDim.x + threadIdx.x) >> 5;
  int lane = threadIdx.x & 31;
  if (w >= N) return;
  int beg = g_rowoff[w], end = g_rowoff[w + 1];
  float4 acc[MM];
#pragma unroll
  for (int m = 0; m < MM; ++m)
    acc[m] = *reinterpret_cast<const float4*>(hin + (m * N + w) * D + lane * 4);
  int k = beg;
  for (; k + 1 < end; k += 2) {
    int s0 = g_csrsrc[k];
    int s1 = g_csrsrc[k + 1];
#pragma unroll
    for (int m = 0; m < MM; ++m) {
      float4 v0 = *reinterpret_cast<const float4*>(hin + (m * N + s0) * D + lane * 4);
      float4 v1 = *reinterpret_cast<const float4*>(hin + (m * N + s1) * D + lane * 4);
      acc[m].x += v0.x + v1.x; acc[m].y += v0.y + v1.y;
      acc[m].z += v0.z + v1.z; acc[m].w += v0.w + v1.w;
    }
  }
  if (k < end) {
    int s0 = g_csrsrc[k];
#pragma unroll
    for (int m = 0; m < MM; ++m) {
      float4 v0 = *reinterpret_cast<const float4*>(hin + (m * N + s0) * D + lane * 4);
      acc[m].x += v0.x; acc[m].y += v0.y; acc[m].z += v0.z; acc[m].w += v0.w;
    }
  }
#pragma unroll
  for (int m = 0; m < MM; ++m)
    *reinterpret_cast<float4*>(zout + (m * N + w) * D + lane * 4) = acc[m];
}

// out[r,:] = act(Z[r,:] @ W + bias) ; W is [128,128] row-major
// 64x128 tile per block, 4 rows x 8 cols per thread, packed f32x2 FMA,
// double-buffered smem staging.
__global__ void __launch_bounds__(256, 3) k_gemm128(int R, const float* __restrict__ Z,
                                                    const float* __restrict__ W,
                                                    const float* __restrict__ bias,
                                                    float* __restrict__ out,
                                                    int doRelu) {
  __shared__ float Zs[2][16][68];   // [buf][BK][BM+pad]
  __shared__ float Ws[2][16][128];  // [buf][BK][BN]
  const int tid = threadIdx.x;
  const int row0 = blockIdx.x * 64;
  const int tr = tid >> 4;        // 0..15 -> rows tr*4..tr*4+3
  const int tc = tid & 15;        // 0..15 -> cols tc*8..tc*8+7
  const int zr = tid >> 2;        // 0..63
  const int zk = (tid & 3) * 4;   // 0,4,8,12
  const int wk = tid >> 4;        // 0..15
  const int wj = (tid & 15) * 8;  // 0..120
  const int gr = row0 + zr;

  ull acc[4][4];
#pragma unroll
  for (int i = 0; i < 4; ++i)
#pragma unroll
    for (int p = 0; p < 4; ++p) acc[i][p] = 0ull;

  // stage chunk 0
  {
    float4 zv = make_float4(0.f, 0.f, 0.f, 0.f);
    if (gr < R) zv = *reinterpret_cast<const float4*>(Z + (size_t)gr * 128 + zk);
    Zs[0][zk + 0][zr] = zv.x; Zs[0][zk + 1][zr] = zv.y;
    Zs[0][zk + 2][zr] = zv.z; Zs[0][zk + 3][zr] = zv.w;
    float4 w0 = *reinterpret_cast<const float4*>(W + (size_t)wk * 128 + wj);
    float4 w1 = *reinterpret_cast<const float4*>(W + (size_t)wk * 128 + wj + 4);
    *reinterpret_cast<float4*>(&Ws[0][wk][wj]) = w0;
    *reinterpret_cast<float4*>(&Ws[0][wk][wj + 4]) = w1;
  }
  __syncthreads();

  int buf = 0;
#pragma unroll 1
  for (int c = 0; c < 8; ++c) {
    float4 nzv, nw0, nw1;
    if (c < 7) {
      int k0 = (c + 1) * 16;
      nzv = make_float4(0.f, 0.f, 0.f, 0.f);
      if (gr < R) nzv = *reinterpret_cast<const float4*>(Z + (size_t)gr * 128 + k0 + zk);
      nw0 = *reinterpret_cast<const float4*>(W + (size_t)(k0 + wk) * 128 + wj);
      nw1 = *reinterpret_cast<const float4*>(W + (size_t)(k0 + wk) * 128 + wj + 4);
    }
#pragma unroll
    for (int kk = 0; kk < 16; ++kk) {
      float4 z4 = *reinterpret_cast<const float4*>(&Zs[buf][kk][tr * 4]);
      ull zz0 = pack2dup(z4.x);
      ull zz1 = pack2dup(z4.y);
      ull zz2 = pack2dup(z4.z);
      ull zz3 = pack2dup(z4.w);
      const ull* wp = reinterpret_cast<const ull*>(&Ws[buf][kk][tc * 8]);
      ull w0 = wp[0], w1 = wp[1], w2 = wp[2], w3 = wp[3];
      acc[0][0] = ffma2(zz0, w0, acc[0][0]);
      acc[0][1] = ffma2(zz0, w1, acc[0][1]);
      acc[0][2] = ffma2(zz0, w2, acc[0][2]);
      acc[0][3] = ffma2(zz0, w3, acc[0][3]);
      acc[1][0] = ffma2(zz1, w0, acc[1][0]);
      acc[1][1] = ffma2(zz1, w1, acc[1][1]);
      acc[1][2] = ffma2(zz1, w2, acc[1][2]);
      acc[1][3] = ffma2(zz1, w3, acc[1][3]);
      acc[2][0] = ffma2(zz2, w0, acc[2][0]);
      acc[2][1] = ffma2(zz2, w1, acc[2][1]);
      acc[2][2] = ffma2(zz2, w2, acc[2][2]);
      acc[2][3] = ffma2(zz2, w3, acc[2][3]);
      acc[3][0] = ffma2(zz3, w0, acc[3][0]);
      acc[3][1] = ffma2(zz3, w1, acc[3][1]);
      acc[3][2] = ffma2(zz3, w2, acc[3][2]);
      acc[3][3] = ffma2(zz3, w3, acc[3][3]);
    }
    if (c < 7) {
      int nb = buf ^ 1;
      Zs[nb][zk + 0][zr] = nzv.x; Zs[nb][zk + 1][zr] = nzv.y;
      Zs[nb][zk + 2][zr] = nzv.z; Zs[nb][zk + 3][zr] = nzv.w;
      *reinterpret_cast<float4*>(&Ws[nb][wk][wj]) = nw0;
      *reinterpret_cast<float4*>(&Ws[nb][wk][wj + 4]) = nw1;
      __syncthreads();
      buf = nb;
    }
  }

  float4 b0 = *reinterpret_cast<const float4*>(bias + tc * 8);
  float4 b1 = *reinterpret_cast<const float4*>(bias + tc * 8 + 4);
  float bb[8] = {b0.x, b0.y, b0.z, b0.w, b1.x, b1.y, b1.z, b1.w};
#pragma unroll
  for (int i = 0; i < 4; ++i) {
    int r = row0 + tr * 4 + i;
    if (r < R) {
      float o[8];
#pragma unroll
      for (int p = 0; p < 4; ++p) {
        float lo, hi;
        unpack2(acc[i][p], lo, hi);
        o[2 * p] = lo + bb[2 * p];
        o[2 * p + 1] = hi + bb[2 * p + 1];
      }
      if (doRelu) {
#pragma unroll
        for (int j = 0; j < 8; ++j) o[j] = fmaxf(o[j], 0.f);
      }
      float4 o0 = make_float4(o[0], o[1], o[2], o[3]);
      float4 o1 = make_float4(o[4], o[5], o[6], o[7]);
      *reinterpret_cast<float4*>(out + (size_t)r * 128 + tc * 8) = o0;
      *reinterpret_cast<float4*>(out + (size_t)r * 128 + tc * 8 + 4) = o1;
    }
  }
}

// pred[n] = h[n,:] . Wd + bd  (one warp per node)
__global__ void k_pred(const float* __restrict__ h, const float* __restrict__ Wd,
                       const float* __restrict__ bd) {
  int w = (blockIdx.x * blockDim.x + threadIdx.x) >> 5;
  int lane = threadIdx.x & 31;
  if (w >= N) return;
  float4 hv = *reinterpret_cast<const float4*>(h + w * D + lane * 4);
  float4 wv = *reinterpret_cast<const float4*>(Wd + lane * 4);
  float s = hv.x * wv.x + hv.y * wv.y + hv.z * wv.z + hv.w * wv.w;
#pragma unroll
  for (int off = 16; off; off >>= 1) s += __shfl_xor_sync(0xffffffffu, s, off);
  if (lane == 0) g_pred[w] = s + bd[0];
}

// per-graph softmax stats (max + sum of exp)
__global__ void k_gstats() {
  int g = blockIdx.x;
  int tid = threadIdx.x;
  int beg = g_gstart[g], end = g_gstart[g + 1];
  __shared__ float red[256];
  float mx = -3.4e38f;
  for (int n = beg + tid; n < end; n += 256) mx = fmaxf(mx, g_pred[n]);
  red[tid] = mx;
  __syncthreads();
  for (int off = 128; off; off >>= 1) {
    if (tid < off) red[tid] = fmaxf(red[tid], red[tid + off]);
    __syncthreads();
  }
  float mxv = red[0];
  __syncthreads();
  float s = 0.f;
  for (int n = beg + tid; n < end; n += 256) s += expf(g_pred[n] - mxv);
  red[tid] = s;
  __syncthreads();
  for (int off = 128; off; off >>= 1) {
    if (tid < off) red[tid] += red[tid + off];
    __syncthreads();
  }
  if (tid == 0) {
    bool ok = beg < end;
    g_gmax[g] = ok ? mxv : 0.f;
    g_gsum[g] = ok ? red[0] : 1.f;
  }
}

// Gumbel-max sampling: one block per (m, graph)
__global__ void k_sample() {
  int b = blockIdx.x;           // b = m*NG + g
  int m = b >> 7;
  int g = b & 127;
  int tid = threadIdx.x;
  int beg = g_gstart[g], end = g_gstart[g + 1];
  if (beg >= end) {
    if (tid == 0) g_anchor[b] = -1;
    return;
  }
  uint2 dk = threefry2x32(0u, 1u, 0u, 1u);  // fold_in(key(1), 1)
  float mxv = g_gmax[g];
  float sv = g_gsum[g];
  float best = -3.4e38f;
  int bid = 0x7fffffff;
  for (int n = beg + tid; n < end; n += 128) {
    float prob = expf(g_pred[n] - mxv) / sv;
    float lp = logf(prob + 1e-15f);
    uint2 r = threefry2x32(dk.x, dk.y, (unsigned)n, (unsigned)(N + n));
    unsigned bits = (m == 0) ? r.x : r.y;
    float u = __uint_as_float((bits >> 9) | 0x3f800000u) - 1.0f;
    float gum = -logf(-logf(u + 1e-12f) + 1e-12f);
    float sc = lp + gum;
    if (sc > best || (sc == best && n < bid)) { best = sc; bid = n; }
  }
  __shared__ float rs[128];
  __shared__ int ri[128];
  rs[tid] = best; ri[tid] = bid;
  __syncthreads();
  for (int off = 64; off; off >>= 1) {
    if (tid < off) {
      if (rs[tid + off] > rs[tid] ||
          (rs[tid + off] == rs[tid] && ri[tid + off] < ri[tid])) {
        rs[tid] = rs[tid + off];
        ri[tid] = ri[tid + off];
      }
    }
    __syncthreads();
  }
  if (tid == 0) g_anchor[b] = ri[0];
}

// bufA[m] = tx (both m)
__global__ void k_copyx() {
  int i = blockIdx.x * blockDim.x + threadIdx.x;
  if (i < N * D) {
    float v = g_tx[i];
    g_bufA[i] = v;
    g_bufA[N * D + i] = v;
  }
}

// apply anchor modulation at sampled nodes: x = tx * (1 + at[1])
__global__ void k_anchor_apply(const float* __restrict__ anchor_table) {
  int b = blockIdx.x;  // m*NG+g
  int d = threadIdx.x;
  int n = g_anchor[b];
  if (n < 0) return;
  int m = b >> 7;
  float f = 1.0f + anchor_table[D + d];
  g_bufA[(m * N + n) * D + d] = g_tx[n * D + d] * f;
}

// mean pool per (m, graph): 256 threads, 2 nodes in flight
__global__ void k_pool(const float* __restrict__ hn) {
  int b = blockIdx.x;  // m*NG+g
  int m = b >> 7;
  int g = b & 127;
  int tid = threadIdx.x;
  int d = tid & 127;
  int half = tid >> 7;
  int beg = g_gstart[g], end = g_gstart[g + 1];
  float acc = 0.f;
  for (int n = beg + half; n < end; n += 2) acc += hn[(m * N + n) * D + d];
  __shared__ float s[128];
  if (half == 1) s[d] = acc;
  __syncthreads();
  if (half == 0) {
    float tot = acc + s[d];
    int c = end - beg;
    g_hg[b * D + d] = tot / (float)max(c, 1);
  }
}

// out[g,t] = mean_m(hg[m,g] @ Wp + bp)
__global__ void k_out(const float* __restrict__ Wp, const float* __restrict__ bp,
                      float* __restrict__ out) {
  int g = blockIdx.x;
  int t = threadIdx.x;
  if (t >= NT) return;
  float acc = 0.f;
  for (int m = 0; m < M; ++m) {
    const float* hg = &g_hg[(m * NG + g) * D];
    float s = 0.f;
#pragma unroll 16
    for (int k = 0; k < D; ++k) s += hg[k] * Wp[k * NT + t];
    acc += s;
  }
  out[g * NT + t] = acc * (1.0f / M) + bp[t];
}

// ---------------- launch ----------------
extern "C" void kernel_launch(void* const* d_in, const int* in_sizes, int n_in,
                              void* d_out, int out_size) {
  const int*   x_idx    = (const int*)d_in[0];
  const int*   edge_src = (const int*)d_in[1];
  const int*   edge_dst = (const int*)d_in[2];
  const int*   batch    = (const int*)d_in[3];
  const float* x_table  = (const float*)d_in[4];
  const float* anchor_t = (const float*)d_in[5];
  const float* Wg       = (const float*)d_in[6];
  const float* bg       = (const float*)d_in[7];
  const float* Wn       = (const float*)d_in[8];
  const float* bn       = (const float*)d_in[9];
  const float* Wd       = (const float*)d_in[10];
  const float* bd       = (const float*)d_in[11];
  const float* Wp       = (const float*)d_in[12];
  const float* bp       = (const float*)d_in[13];
  float* out = (float*)d_out;

  float *txp, *bufA, *bufB;
  cudaGetSymbolAddress((void**)&txp, g_tx);
  cudaGetSymbolAddress((void**)&bufA, g_bufA);
  cudaGetSymbolAddress((void**)&bufB, g_bufB);

  const int AGG_GRID = (N * 32 + 255) / 256;        // one warp per node
  const int GEMM1 = (N + 63) / 64;                  // 50000 rows
  const int GEMM2 = (M * N + 63) / 64;              // 100000 rows

  // ---- prep: embed + CSR(dst) build ----
  k_embed<<<N, D>>>(x_idx, batch, x_table);
  k_hist<<<(E + 255) / 256, 256>>>(edge_dst);
  k_scan<<<1, 1024>>>();
  k_scatter<<<(E + 255) / 256, 256>>>(edge_src, edge_dst);

  // ---- GNN pass 1 (M collapsed to 1) ----
  k_agg<1><<<AGG_GRID, 256>>>(txp, bufB);
  k_gemm128<<<GEMM1, 256>>>(N, bufB, Wg, bg, bufA, 1);
  k_agg<1><<<AGG_GRID, 256>>>(bufA, bufB);
  k_gemm128<<<GEMM1, 256>>>(N, bufB, Wg + D * D, bg + D, bufA, 1);

  // ---- distance head + per-graph softmax + Gumbel-max sample ----
  k_pred<<<AGG_GRID, 256>>>(bufA, Wd, bd);
  k_gstats<<<NG, 256>>>();
  k_sample<<<M * NG, 128>>>();

  // ---- anchored re-embed ----
  k_copyx<<<(N * D + 255) / 256, 256>>>();
  k_anchor_apply<<<M * NG, D>>>(anchor_t);

  // ---- GNN pass 2 (M = 2) ----
  k_agg<2><<<AGG_GRID, 256>>>(bufA, bufB);
  k_gemm128<<<GEMM2, 256>>>(M * N, bufB, Wg, bg, bufA, 1);
  k_agg<2><<<AGG_GRID, 256>>>(bufA, bufB);
  k_gemm128<<<GEMM2, 256>>>(M * N, bufB, Wg + D * D, bg + D, bufA, 1);

  // ---- node MLP + pool + task head ----
  k_gemm128<<<GEMM2, 256>>>(M * N, bufA, Wn, bn, bufB, 1);
  k_pool<<<M * NG, 256>>>(bufB);
  k_out<<<NG, 32>>>(Wp, bp, out);
}

// round 3
// speedup vs baseline: 1.1230x; 1.0871x over previous
#include <cuda_runtime.h>
#include <stdint.h>

// ---------------- problem constants ----------------
constexpr int N  = 50000;
constexpr int E  = 800000;
constexpr int NG = 128;
constexpr int D  = 128;
constexpr int M  = 2;
constexpr int NT = 10;

typedef unsigned long long ull;

// ---------------- device scratch ----------------
__device__ float g_tx[N * D];
__device__ float g_z1[N * D];
__device__ float g_h1[N * D];
__device__ float g_z2[N * D];
__device__ float g_h2[N * D];
__device__ float g_hn[N * D];
__device__ float g_dz[M * N * D];
__device__ float g_dh1[M * N * D];
__device__ float g_dh2[M * N * D];
__device__ float g_dhn[M * N * D];
__device__ int   g_deg[N];
__device__ int   g_rowoff[N + 1];
__device__ int   g_cursor[N];
__device__ int   g_csrsrc[E];
__device__ int   g_gstart[NG + 1];
__device__ float g_pred[N];
__device__ float g_gmax[NG];
__device__ float g_gsum[NG];
__device__ int   g_anchor[M * NG];
__device__ float g_hgb[NG * D];
__device__ float g_hg[M * NG * D];
__device__ unsigned char g_fA[M * N];
__device__ unsigned char g_f1[M * N];
__device__ unsigned char g_f2[M * N];
__device__ int   g_list1[M * N];
__device__ int   g_list2[M * N];
__device__ int   g_hitE[M * E];
__device__ int   g_cnt[8];  // [m]=cnt1, [2+m]=hit1, [4+m]=cnt2, [6+m]=hit2

// ---------------- f32x2 helpers ----------------
__device__ __forceinline__ ull ffma2(ull a, ull b, ull c) {
  ull d;
  asm("fma.rn.f32x2 %0, %1, %2, %3;" : "=l"(d) : "l"(a), "l"(b), "l"(c));
  return d;
}
__device__ __forceinline__ ull pack2dup(float x) {
  ull r;
  asm("mov.b64 %0, {%1, %1};" : "=l"(r) : "f"(x));
  return r;
}
__device__ __forceinline__ void unpack2(ull v, float& lo, float& hi) {
  asm("mov.b64 {%0, %1}, %2;" : "=f"(lo), "=f"(hi) : "l"(v));
}

// ---------------- threefry2x32 (exact JAX) ----------------
__device__ __forceinline__ uint2 threefry2x32(unsigned k0, unsigned k1,
                                              unsigned x0, unsigned x1) {
  unsigned k2 = k0 ^ k1 ^ 0x1BD11BDAu;
  x0 += k0; x1 += k1;
#define TF_ROT(x, d) (((x) << (d)) | ((x) >> (32 - (d))))
#define TF_RND(r) { x0 += x1; x1 = TF_ROT(x1, r); x1 ^= x0; }
  TF_RND(13) TF_RND(15) TF_RND(26) TF_RND(6)
  x0 += k1; x1 += k2 + 1u;
  TF_RND(17) TF_RND(29) TF_RND(16) TF_RND(24)
  x0 += k2; x1 += k0 + 2u;
  TF_RND(13) TF_RND(15) TF_RND(26) TF_RND(6)
  x0 += k0; x1 += k1 + 3u;
  TF_RND(17) TF_RND(29) TF_RND(16) TF_RND(24)
  x0 += k1; x1 += k2 + 4u;
  TF_RND(13) TF_RND(15) TF_RND(26) TF_RND(6)
  x0 += k2; x1 += k0 + 5u;
#undef TF_RND
#undef TF_ROT
  return make_uint2(x0, x1);
}

// ---------------- base kernels ----------------
__global__ void k_embed(const int* __restrict__ x_idx,
                        const int* __restrict__ batch,
                        const float* __restrict__ x_table) {
  int n = blockIdx.x;
  int d = threadIdx.x;
  g_tx[n * D + d] = x_table[x_idx[n] * D + d];
  if (d == 0) {
    g_deg[n] = 0;
    int b = batch[n];
    if (n == 0) {
      for (int g = 0; g <= b; ++g) g_gstart[g] = 0;
    } else {
      int pb = batch[n - 1];
      for (int g = pb + 1; g <= b; ++g) g_gstart[g] = n;
    }
    if (n == N - 1) {
      for (int g = b + 1; g <= NG; ++g) g_gstart[g] = N;
    }
  }
}

__global__ void k_hist(const int* __restrict__ edge_dst) {
  int e = blockIdx.x * blockDim.x + threadIdx.x;
  if (e < E) atomicAdd(&g_deg[edge_dst[e]], 1);
}

__global__ void k_scan() {
  __shared__ int sums[1024];
  int tid = threadIdx.x;
  const int CH = (N + 1023) / 1024;
  int beg = tid * CH;
  int end = min(beg + CH, N);
  int s = 0;
  for (int i = beg; i < end; ++i) s += g_deg[i];
  sums[tid] = s;
  __syncthreads();
  for (int off = 1; off < 1024; off <<= 1) {
    int v = (tid >= off) ? sums[tid - off] : 0;
    __syncthreads();
    sums[tid] += v;
    __syncthreads();
  }
  int pre = (tid == 0) ? 0 : sums[tid - 1];
  for (int i = beg; i < end; ++i) {
    g_rowoff[i] = pre;
    g_cursor[i] = pre;
    pre += g_deg[i];
  }
  if (tid == 1023) g_rowoff[N] = sums[1023];
}

__global__ void k_scatter(const int* __restrict__ edge_src,
                          const int* __restrict__ edge_dst) {
  int e = blockIdx.x * blockDim.x + threadIdx.x;
  if (e < E) {
    int d = edge_dst[e];
    int pos = atomicAdd(&g_cursor[d], 1);
    g_csrsrc[pos] = edge_src[e];
  }
}

// z[n,:] = h[n,:] + sum_{e: dst==n} h[src,:]   (one warp per node)
__global__ void __launch_bounds__(256) k_agg(const float* __restrict__ hin,
                                             float* __restrict__ zout) {
  int w = (blockIdx.x * blockDim.x + threadIdx.x) >> 5;
  int lane = threadIdx.x & 31;
  if (w >= N) return;
  int beg = g_rowoff[w], end = g_rowoff[w + 1];
  float4 acc = *reinterpret_cast<const float4*>(hin + (size_t)w * D + lane * 4);
  int k = beg;
  for (; k + 1 < end; k += 2) {
    int s0 = g_csrsrc[k];
    int s1 = g_csrsrc[k + 1];
    float4 v0 = *reinterpret_cast<const float4*>(hin + (size_t)s0 * D + lane * 4);
    float4 v1 = *reinterpret_cast<const float4*>(hin + (size_t)s1 * D + lane * 4);
    acc.x += v0.x + v1.x; acc.y += v0.y + v1.y;
    acc.z += v0.z + v1.z; acc.w += v0.w + v1.w;
  }
  if (k < end) {
    int s0 = g_csrsrc[k];
    float4 v0 = *reinterpret_cast<const float4*>(hin + (size_t)s0 * D + lane * 4);
    acc.x += v0.x; acc.y += v0.y; acc.z += v0.z; acc.w += v0.w;
  }
  *reinterpret_cast<float4*>(zout + (size_t)w * D + lane * 4) = acc;
}

// dense: out[r,:] = relu(Z[r,:] @ W + bias), double-buffered, FFMA2
__global__ void __launch_bounds__(256, 3) k_gemm128(int R, const float* __restrict__ Z,
                                                    const float* __restrict__ W,
                                                    const float* __restrict__ bias,
                                                    float* __restrict__ out) {
  __shared__ float Zs[2][16][68];
  __shared__ float Ws[2][16][128];
  const int tid = threadIdx.x;
  const int row0 = blockIdx.x * 64;
  const int tr = tid >> 4;
  const int tc = tid & 15;
  const int zr = tid >> 2;
  const int zk = (tid & 3) * 4;
  const int wk = tid >> 4;
  const int wj = (tid & 15) * 8;
  const int gr = row0 + zr;

  ull acc[4][4];
#pragma unroll
  for (int i = 0; i < 4; ++i)
#pragma unroll
    for (int p = 0; p < 4; ++p) acc[i][p] = 0ull;

  {
    float4 zv = make_float4(0.f, 0.f, 0.f, 0.f);
    if (gr < R) zv = *reinterpret_cast<const float4*>(Z + (size_t)gr * 128 + zk);
    Zs[0][zk + 0][zr] = zv.x; Zs[0][zk + 1][zr] = zv.y;
    Zs[0][zk + 2][zr] = zv.z; Zs[0][zk + 3][zr] = zv.w;
    float4 w0 = *reinterpret_cast<const float4*>(W + (size_t)wk * 128 + wj);
    float4 w1 = *reinterpret_cast<const float4*>(W + (size_t)wk * 128 + wj + 4);
    *reinterpret_cast<float4*>(&Ws[0][wk][wj]) = w0;
    *reinterpret_cast<float4*>(&Ws[0][wk][wj + 4]) = w1;
  }
  __syncthreads();

  int buf = 0;
#pragma unroll 1
  for (int c = 0; c < 8; ++c) {
    float4 nzv, nw0, nw1;
    if (c < 7) {
      int k0 = (c + 1) * 16;
      nzv = make_float4(0.f, 0.f, 0.f, 0.f);
      if (gr < R) nzv = *reinterpret_cast<const float4*>(Z + (size_t)gr * 128 + k0 + zk);
      nw0 = *reinterpret_cast<const float4*>(W + (size_t)(k0 + wk) * 128 + wj);
      nw1 = *reinterpret_cast<const float4*>(W + (size_t)(k0 + wk) * 128 + wj + 4);
    }
#pragma unroll
    for (int kk = 0; kk < 16; ++kk) {
      float4 z4 = *reinterpret_cast<const float4*>(&Zs[buf][kk][tr * 4]);
      ull zz0 = pack2dup(z4.x);
      ull zz1 = pack2dup(z4.y);
      ull zz2 = pack2dup(z4.z);
      ull zz3 = pack2dup(z4.w);
      const ull* wp = reinterpret_cast<const ull*>(&Ws[buf][kk][tc * 8]);
      ull w0 = wp[0], w1 = wp[1], w2 = wp[2], w3 = wp[3];
      acc[0][0] = ffma2(zz0, w0, acc[0][0]);
      acc[0][1] = ffma2(zz0, w1, acc[0][1]);
      acc[0][2] = ffma2(zz0, w2, acc[0][2]);
      acc[0][3] = ffma2(zz0, w3, acc[0][3]);
      acc[1][0] = ffma2(zz1, w0, acc[1][0]);
      acc[1][1] = ffma2(zz1, w1, acc[1][1]);
      acc[1][2] = ffma2(zz1, w2, acc[1][2]);
      acc[1][3] = ffma2(zz1, w3, acc[1][3]);
      acc[2][0] = ffma2(zz2, w0, acc[2][0]);
      acc[2][1] = ffma2(zz2, w1, acc[2][1]);
      acc[2][2] = ffma2(zz2, w2, acc[2][2]);
      acc[2][3] = ffma2(zz2, w3, acc[2][3]);
      acc[3][0] = ffma2(zz3, w0, acc[3][0]);
      acc[3][1] = ffma2(zz3, w1, acc[3][1]);
      acc[3][2] = ffma2(zz3, w2, acc[3][2]);
      acc[3][3] = ffma2(zz3, w3, acc[3][3]);
    }
    if (c < 7) {
      int nb = buf ^ 1;
      Zs[nb][zk + 0][zr] = nzv.x; Zs[nb][zk + 1][zr] = nzv.y;
      Zs[nb][zk + 2][zr] = nzv.z; Zs[nb][zk + 3][zr] = nzv.w;
      *reinterpret_cast<float4*>(&Ws[nb][wk][wj]) = nw0;
      *reinterpret_cast<float4*>(&Ws[nb][wk][wj + 4]) = nw1;
      __syncthreads();
      buf = nb;
    }
  }

  float4 b0 = *reinterpret_cast<const float4*>(bias + tc * 8);
  float4 b1 = *reinterpret_cast<const float4*>(bias + tc * 8 + 4);
  float bb[8] = {b0.x, b0.y, b0.z, b0.w, b1.x, b1.y, b1.z, b1.w};
#pragma unroll
  for (int i = 0; i < 4; ++i) {
    int r = row0 + tr * 4 + i;
    if (r < R) {
      float o[8];
#pragma unroll
      for (int p = 0; p < 4; ++p) {
        float lo, hi;
        unpack2(acc[i][p], lo, hi);
        o[2 * p] = fmaxf(lo + bb[2 * p], 0.f);
        o[2 * p + 1] = fmaxf(hi + bb[2 * p + 1], 0.f);
      }
      *reinterpret_cast<float4*>(out + (size_t)r * 128 + tc * 8) =
          make_float4(o[0], o[1], o[2], o[3]);
      *reinterpret_cast<float4*>(out + (size_t)r * 128 + tc * 8 + 4) =
          make_float4(o[4], o[5], o[6], o[7]);
    }
  }
}

// list GEMM: for rows in list[m]: Out[row] = relu((Zb[row]+Dz[m][row])@W + b) - Sub[row]
__global__ void __launch_bounds__(256) k_gemm_list(
    const int* __restrict__ listb, const int* __restrict__ cntp, int cntoff,
    const float* __restrict__ Zb, const float* __restrict__ Dzb,
    const float* __restrict__ W, const float* __restrict__ bias,
    const float* __restrict__ Sub, float* __restrict__ Outb) {
  const int m = blockIdx.y;
  const int cnt = cntp[cntoff + m];
  const int t0 = blockIdx.x * 64;
  if (t0 >= cnt) return;
  const int* list = listb + m * N;
  const float* Dz = Dzb + (size_t)m * N * D;
  float* Out = Outb + (size_t)m * N * D;
  __shared__ int lrow[64];
  __shared__ float Zs[16][68];
  __shared__ float Ws[16][128];
  const int tid = threadIdx.x;
  if (tid < 64) lrow[tid] = (t0 + tid < cnt) ? list[t0 + tid] : -1;
  __syncthreads();
  const int tr = tid >> 4;
  const int tc = tid & 15;
  const int zr = tid >> 2;
  const int zk = (tid & 3) * 4;
  const int wk = tid >> 4;
  const int wj = (tid & 15) * 8;
  const int zrow = lrow[zr];
  ull acc[4][4];
#pragma unroll
  for (int i = 0; i < 4; ++i)
#pragma unroll
    for (int p = 0; p < 4; ++p) acc[i][p] = 0ull;

#pragma unroll 1
  for (int c = 0; c < 8; ++c) {
    int k0 = c * 16;
    float4 zv = make_float4(0.f, 0.f, 0.f, 0.f);
    if (zrow >= 0) {
      float4 a = *reinterpret_cast<const float4*>(Zb + (size_t)zrow * 128 + k0 + zk);
      float4 dv = *reinterpret_cast<const float4*>(Dz + (size_t)zrow * 128 + k0 + zk);
      zv = make_float4(a.x + dv.x, a.y + dv.y, a.z + dv.z, a.w + dv.w);
    }
    Zs[zk + 0][zr] = zv.x; Zs[zk + 1][zr] = zv.y;
    Zs[zk + 2][zr] = zv.z; Zs[zk + 3][zr] = zv.w;
    float4 w0 = *reinterpret_cast<const float4*>(W + (size_t)(k0 + wk) * 128 + wj);
    float4 w1 = *reinterpret_cast<const float4*>(W + (size_t)(k0 + wk) * 128 + wj + 4);
    *reinterpret_cast<float4*>(&Ws[wk][wj]) = w0;
    *reinterpret_cast<float4*>(&Ws[wk][wj + 4]) = w1;
    __syncthreads();
#pragma unroll
    for (int kk = 0; kk < 16; ++kk) {
      float4 z4 = *reinterpret_cast<const float4*>(&Zs[kk][tr * 4]);
      ull zz0 = pack2dup(z4.x);
      ull zz1 = pack2dup(z4.y);
      ull zz2 = pack2dup(z4.z);
      ull zz3 = pack2dup(z4.w);
      const ull* wp = reinterpret_cast<const ull*>(&Ws[kk][tc * 8]);
      ull w0 = wp[0], w1 = wp[1], w2 = wp[2], w3 = wp[3];
      acc[0][0] = ffma2(zz0, w0, acc[0][0]);
      acc[0][1] = ffma2(zz0, w1, acc[0][1]);
      acc[0][2] = ffma2(zz0, w2, acc[0][2]);
      acc[0][3] = ffma2(zz0, w3, acc[0][3]);
      acc[1][0] = ffma2(zz1, w0, acc[1][0]);
      acc[1][1] = ffma2(zz1, w1, acc[1][1]);
      acc[1][2] = ffma2(zz1, w2, acc[1][2]);
      acc[1][3] = ffma2(zz1, w3, acc[1][3]);
      acc[2][0] = ffma2(zz2, w0, acc[2][0]);
      acc[2][1] = ffma2(zz2, w1, acc[2][1]);
      acc[2][2] = ffma2(zz2, w2, acc[2][2]);
      acc[2][3] = ffma2(zz2, w3, acc[2][3]);
      acc[3][0] = ffma2(zz3, w0, acc[3][0]);
      acc[3][1] = ffma2(zz3, w1, acc[3][1]);
      acc[3][2] = ffma2(zz3, w2, acc[3][2]);
      acc[3][3] = ffma2(zz3, w3, acc[3][3]);
    }
    __syncthreads();
  }

  float4 b0 = *reinterpret_cast<const float4*>(bias + tc * 8);
  float4 b1 = *reinterpret_cast<const float4*>(bias + tc * 8 + 4);
  float bb[8] = {b0.x, b0.y, b0.z, b0.w, b1.x, b1.y, b1.z, b1.w};
#pragma unroll
  for (int i = 0; i < 4; ++i) {
    int row = lrow[tr * 4 + i];
    if (row >= 0) {
      float4 s0 = *reinterpret_cast<const float4*>(Sub + (size_t)row * 128 + tc * 8);
      float4 s1 = *reinterpret_cast<const float4*>(Sub + (size_t)row * 128 + tc * 8 + 4);
      float ss[8] = {s0.x, s0.y, s0.z, s0.w, s1.x, s1.y, s1.z, s1.w};
      float o[8];
#pragma unroll
      for (int p = 0; p < 4; ++p) {
        float lo, hi;
        unpack2(acc[i][p], lo, hi);
        o[2 * p] = fmaxf(lo + bb[2 * p], 0.f) - ss[2 * p];
        o[2 * p + 1] = fmaxf(hi + bb[2 * p + 1], 0.f) - ss[2 * p + 1];
      }
      *reinterpret_cast<float4*>(Out + (size_t)row * 128 + tc * 8) =
          make_float4(o[0], o[1], o[2], o[3]);
      *reinterpret_cast<float4*>(Out + (size_t)row * 128 + tc * 8 + 4) =
          make_float4(o[4], o[5], o[6], o[7]);
    }
  }
}

// ---------------- sampling path (unchanged, validated) ----------------
__global__ void k_pred(const float* __restrict__ h, const float* __restrict__ Wd,
                       const float* __restrict__ bd) {
  int w = (blockIdx.x * blockDim.x + threadIdx.x) >> 5;
  int lane = threadIdx.x & 31;
  if (w >= N) return;
  float4 hv = *reinterpret_cast<const float4*>(h + (size_t)w * D + lane * 4);
  float4 wv = *reinterpret_cast<const float4*>(Wd + lane * 4);
  float s = hv.x * wv.x + hv.y * wv.y + hv.z * wv.z + hv.w * wv.w;
#pragma unroll
  for (int off = 16; off; off >>= 1) s += __shfl_xor_sync(0xffffffffu, s, off);
  if (lane == 0) g_pred[w] = s + bd[0];
}

__global__ void k_gstats() {
  int g = blockIdx.x;
  int tid = threadIdx.x;
  int beg = g_gstart[g], end = g_gstart[g + 1];
  __shared__ float red[256];
  float mx = -3.4e38f;
  for (int n = beg + tid; n < end; n += 256) mx = fmaxf(mx, g_pred[n]);
  red[tid] = mx;
  __syncthreads();
  for (int off = 128; off; off >>= 1) {
    if (tid < off) red[tid] = fmaxf(red[tid], red[tid + off]);
    __syncthreads();
  }
  float mxv = red[0];
  __syncthreads();
  float s = 0.f;
  for (int n = beg + tid; n < end; n += 256) s += expf(g_pred[n] - mxv);
  red[tid] = s;
  __syncthreads();
  for (int off = 128; off; off >>= 1) {
    if (tid < off) red[tid] += red[tid + off];
    __syncthreads();
  }
  if (tid == 0) {
    bool ok = beg < end;
    g_gmax[g] = ok ? mxv : 0.f;
    g_gsum[g] = ok ? red[0] : 1.f;
  }
}

__global__ void k_sample() {
  int b = blockIdx.x;
  int m = b >> 7;
  int g = b & 127;
  int tid = threadIdx.x;
  int beg = g_gstart[g], end = g_gstart[g + 1];
  if (beg >= end) {
    if (tid == 0) g_anchor[b] = -1;
    return;
  }
  uint2 dk = threefry2x32(0u, 1u, 0u, 1u);
  float mxv = g_gmax[g];
  float sv = g_gsum[g];
  float best = -3.4e38f;
  int bid = 0x7fffffff;
  for (int n = beg + tid; n < end; n += 128) {
    float prob = expf(g_pred[n] - mxv) / sv;
    float lp = logf(prob + 1e-15f);
    uint2 r = threefry2x32(dk.x, dk.y, (unsigned)n, (unsigned)(N + n));
    unsigned bits = (m == 0) ? r.x : r.y;
    float u = __uint_as_float((bits >> 9) | 0x3f800000u) - 1.0f;
    float gum = -logf(-logf(u + 1e-12f) + 1e-12f);
    float sc = lp + gum;
    if (sc > best || (sc == best && n < bid)) { best = sc; bid = n; }
  }
  __shared__ float rs[128];
  __shared__ int ri[128];
  rs[tid] = best; ri[tid] = bid;
  __syncthreads();
  for (int off = 64; off; off >>= 1) {
    if (tid < off) {
      if (rs[tid + off] > rs[tid] ||
          (rs[tid + off] == rs[tid] && ri[tid + off] < ri[tid])) {
        rs[tid] = rs[tid + off];
        ri[tid] = ri[tid + off];
      }
    }
    __syncthreads();
  }
  if (tid == 0) g_anchor[b] = ri[0];
}

// ---------------- pass-2 sparse machinery ----------------
__global__ void k_mclear() {
  int n = blockIdx.x * blockDim.x + threadIdx.x;
  if (n < N) {
    g_fA[n] = 0; g_fA[N + n] = 0;
    g_f1[n] = 0; g_f1[N + n] = 0;
    g_f2[n] = 0; g_f2[N + n] = 0;
  }
  if (n < 8) g_cnt[n] = 0;
}

__global__ void k_mark_anchor() {
  int t = blockIdx.x * blockDim.x + threadIdx.x;
  if (t < M * NG) {
    int a = g_anchor[t];
    int m = t >> 7;
    if (a >= 0) { g_fA[m * N + a] = 1; g_f1[m * N + a] = 1; }
  }
}

__global__ void k_mark_edges1(const int* __restrict__ es, const int* __restrict__ ed) {
  int e = blockIdx.x * blockDim.x + threadIdx.x;
  if (e >= E) return;
  int s = es[e], dd = ed[e];
#pragma unroll
  for (int m = 0; m < M; ++m) {
    if (g_fA[m * N + s]) {
      g_f1[m * N + dd] = 1;
      int p = atomicAdd(&g_cnt[2 + m], 1);
      g_hitE[m * E + p] = e;
    }
  }
}

__global__ void k_compact1() {
  int n = blockIdx.x * blockDim.x + threadIdx.x;
  if (n >= N) return;
#pragma unroll
  for (int m = 0; m < M; ++m) {
    if (g_f1[m * N + n]) {
      int p = atomicAdd(&g_cnt[m], 1);
      g_list1[m * N + p] = n;
    }
  }
}

__global__ void k_mark_edges2(const int* __restrict__ es, const int* __restrict__ ed) {
  int e = blockIdx.x * blockDim.x + threadIdx.x;
  if (e >= E) return;
  int s = es[e], dd = ed[e];
#pragma unroll
  for (int m = 0; m < M; ++m) {
    if (g_f1[m * N + s]) {
      g_f2[m * N + dd] = 1;
      int p = atomicAdd(&g_cnt[6 + m], 1);
      g_hitE[m * E + p] = e;
    }
  }
}

__global__ void k_compact2() {
  int n = blockIdx.x * blockDim.x + threadIdx.x;
  if (n >= N) return;
#pragma unroll
  for (int m = 0; m < M; ++m) {
    if (g_f1[m * N + n] || g_f2[m * N + n]) {
      int p = atomicAdd(&g_cnt[4 + m], 1);
      g_list2[m * N + p] = n;
    }
  }
}

// zero dz rows of list (which: 0 -> list1/cnt[0..], 1 -> list2/cnt[4..])
__global__ void k_zero_rows(int which) {
  int m = blockIdx.y;
  const int* list = (which ? g_list2 : g_list1) + m * N;
  int cnt = g_cnt[(which ? 4 : 0) + m];
  int w = blockIdx.x * 8 + (threadIdx.x >> 5);
  int lane = threadIdx.x & 31;
  float* dz = g_dz + (size_t)m * N * D;
  for (int i = w; i < cnt; i += 256 * 8) {
    int row = list[i];
    *reinterpret_cast<float4*>(dz + (size_t)row * D + lane * 4) =
        make_float4(0.f, 0.f, 0.f, 0.f);
  }
}

// dz[a] = tx[a] * at1  (anchor self term; plain store onto zeroed rows)
__global__ void k_self1(const float* __restrict__ at) {
  int m = blockIdx.y;
  int g = blockIdx.x;
  int a = g_anchor[m * NG + g];
  if (a < 0) return;
  int lane = threadIdx.x;
  float4 t = *reinterpret_cast<const float4*>(g_tx + (size_t)a * D + lane * 4);
  float4 f = *reinterpret_cast<const float4*>(at + D + lane * 4);
  *reinterpret_cast<float4*>(g_dz + ((size_t)m * N + a) * D + lane * 4) =
      make_float4(t.x * f.x, t.y * f.y, t.z * f.z, t.w * f.w);
}

// dz[dst] += tx[src]*at1 for hit edges (anchored src)
__global__ void k_edge_add1(const int* __restrict__ es, const int* __restrict__ ed,
                            const float* __restrict__ at) {
  int m = blockIdx.y;
  int cnt = g_cnt[2 + m];
  int w = blockIdx.x * 8 + (threadIdx.x >> 5);
  int lane = threadIdx.x & 31;
  float4 f = *reinterpret_cast<const float4*>(at + D + lane * 4);
  float* dz = g_dz + (size_t)m * N * D;
  for (int i = w; i < cnt; i += 256 * 8) {
    int e = g_hitE[m * E + i];
    int s = es[e], dd = ed[e];
    float4 t = *reinterpret_cast<const float4*>(g_tx + (size_t)s * D + lane * 4);
    float* p = dz + (size_t)dd * D + lane * 4;
    atomicAdd(p + 0, t.x * f.x);
    atomicAdd(p + 1, t.y * f.y);
    atomicAdd(p + 2, t.z * f.z);
    atomicAdd(p + 3, t.w * f.w);
  }
}

// dz[n] = dh1[n] for n in list1 (self term layer 2; plain store onto zeroed rows)
__global__ void k_self2() {
  int m = blockIdx.y;
  int cnt = g_cnt[m];
  int w = blockIdx.x * 8 + (threadIdx.x >> 5);
  int lane = threadIdx.x & 31;
  const float* dh1 = g_dh1 + (size_t)m * N * D;
  float* dz = g_dz + (size_t)m * N * D;
  for (int i = w; i < cnt; i += 256 * 8) {
    int row = g_list1[m * N + i];
    float4 v = *reinterpret_cast<const float4*>(dh1 + (size_t)row * D + lane * 4);
    *reinterpret_cast<float4*>(dz + (size_t)row * D + lane * 4) = v;
  }
}

// dz[dst] += dh1[src] for hit edges (src in A1)
__global__ void k_edge_add2(const int* __restrict__ es, const int* __restrict__ ed) {
  int m = blockIdx.y;
  int cnt = g_cnt[6 + m];
  int w = blockIdx.x * 8 + (threadIdx.x >> 5);
  int lane = threadIdx.x & 31;
  const float* dh1 = g_dh1 + (size_t)m * N * D;
  float* dz = g_dz + (size_t)m * N * D;
  for (int i = w; i < cnt; i += 256 * 8) {
    int e = g_hitE[m * E + i];
    int s = es[e], dd = ed[e];
    float4 v = *reinterpret_cast<const float4*>(dh1 + (size_t)s * D + lane * 4);
    float* p = dz + (size_t)dd * D + lane * 4;
    atomicAdd(p + 0, v.x);
    atomicAdd(p + 1, v.y);
    atomicAdd(p + 2, v.z);
    atomicAdd(p + 3, v.w);
  }
}

// base mean pool over all nodes
__global__ void k_poolb() {
  int g = blockIdx.x;
  int tid = threadIdx.x;
  int d = tid & 127;
  int half = tid >> 7;
  int beg = g_gstart[g], end = g_gstart[g + 1];
  float acc = 0.f;
  for (int n = beg + half; n < end; n += 2) acc += g_hn[(size_t)n * D + d];
  __shared__ float s[128];
  if (half == 1) s[d] = acc;
  __syncthreads();
  if (half == 0) {
    float tot = acc + s[d];
    int c = end - beg;
    g_hgb[g * D + d] = tot / (float)max(c, 1);
  }
}

__global__ void k_copy_hg() {
  int i = blockIdx.x * blockDim.x + threadIdx.x;
  if (i < M * NG * D) g_hg[i] = g_hgb[i % (NG * D)];
}

// hg[m,g] += dhn[n]/cnt for n in list2[m]
__global__ void k_pool_delta(const int* __restrict__ batch) {
  int m = blockIdx.y;
  int cnt = g_cnt[4 + m];
  int d = threadIdx.x;
  const float* dhn = g_dhn + (size_t)m * N * D;
  for (int i = blockIdx.x; i < cnt; i += gridDim.x) {
    int n = g_list2[m * N + i];
    int g = batch[n];
    int c = g_gstart[g + 1] - g_gstart[g];
    float inv = 1.0f / (float)max(c, 1);
    atomicAdd(&g_hg[(m * NG + g) * D + d], dhn[(size_t)n * D + d] * inv);
  }
}

__global__ void k_out(const float* __restrict__ Wp, const float* __restrict__ bp,
                      float* __restrict__ out) {
  int g = blockIdx.x;
  int t = threadIdx.x;
  if (t >= NT) return;
  float acc = 0.f;
  for (int m = 0; m < M; ++m) {
    const float* hg = &g_hg[(m * NG + g) * D];
    float s = 0.f;
#pragma unroll 16
    for (int k = 0; k < D; ++k) s += hg[k] * Wp[k * NT + t];
    acc += s;
  }
  out[g * NT + t] = acc * (1.0f / M) + bp[t];
}

// ---------------- launch ----------------
extern "C" void kernel_launch(void* const* d_in, const int* in_sizes, int n_in,
                              void* d_out, int out_size) {
  const int*   x_idx    = (const int*)d_in[0];
  const int*   edge_src = (const int*)d_in[1];
  const int*   edge_dst = (const int*)d_in[2];
  const int*   batch    = (const int*)d_in[3];
  const float* x_table  = (const float*)d_in[4];
  const float* anchor_t = (const float*)d_in[5];
  const float* Wg       = (const float*)d_in[6];
  const float* bg       = (const float*)d_in[7];
  const float* Wn       = (const float*)d_in[8];
  const float* bn       = (const float*)d_in[9];
  const float* Wd       = (const float*)d_in[10];
  const float* bd       = (const float*)d_in[11];
  const float* Wp       = (const float*)d_in[12];
  const float* bp       = (const float*)d_in[13];
  float* out = (float*)d_out;

  float *txp, *z1, *h1, *z2, *h2, *hn, *dz, *dh1, *dh2, *dhn;
  int *list1, *list2, *cnt;
  cudaGetSymbolAddress((void**)&txp, g_tx);
  cudaGetSymbolAddress((void**)&z1, g_z1);
  cudaGetSymbolAddress((void**)&h1, g_h1);
  cudaGetSymbolAddress((void**)&z2, g_z2);
  cudaGetSymbolAddress((void**)&h2, g_h2);
  cudaGetSymbolAddress((void**)&hn, g_hn);
  cudaGetSymbolAddress((void**)&dz, g_dz);
  cudaGetSymbolAddress((void**)&dh1, g_dh1);
  cudaGetSymbolAddress((void**)&dh2, g_dh2);
  cudaGetSymbolAddress((void**)&dhn, g_dhn);
  cudaGetSymbolAddress((void**)&list1, g_list1);
  cudaGetSymbolAddress((void**)&list2, g_list2);
  cudaGetSymbolAddress((void**)&cnt, g_cnt);

  const int AGG_GRID = (N * 32 + 255) / 256;
  const int GEMM1 = (N + 63) / 64;
  const dim3 GL(GEMM1, 2);
  const dim3 SP(256, 2);

  // ---- prep ----
  k_embed<<<N, D>>>(x_idx, batch, x_table);
  k_hist<<<(E + 255) / 256, 256>>>(edge_dst);
  k_scan<<<1, 1024>>>();
  k_scatter<<<(E + 255) / 256, 256>>>(edge_src, edge_dst);

  // ---- pass 1 (base, m-independent) ----
  k_agg<<<AGG_GRID, 256>>>(txp, z1);
  k_gemm128<<<GEMM1, 256>>>(N, z1, Wg, bg, h1);
  k_agg<<<AGG_GRID, 256>>>(h1, z2);
  k_gemm128<<<GEMM1, 256>>>(N, z2, Wg + D * D, bg + D, h2);

  // ---- sampling ----
  k_pred<<<AGG_GRID, 256>>>(h2, Wd, bd);
  k_gstats<<<NG, 256>>>();
  k_sample<<<M * NG, 128>>>();

  // ---- base node MLP + base pool ----
  k_gemm128<<<GEMM1, 256>>>(N, h2, Wn, bn, hn);
  k_poolb<<<NG, 256>>>();
  k_copy_hg<<<(M * NG * D + 255) / 256, 256>>>();

  // ---- pass 2: sparse deltas, both m ----
  k_mclear<<<(N + 255) / 256, 256>>>();
  k_mark_anchor<<<1, M * NG>>>();
  k_mark_edges1<<<(E + 255) / 256, 256>>>(edge_src, edge_dst);
  k_compact1<<<(N + 255) / 256, 256>>>();
  k_zero_rows<<<SP, 256>>>(0);
  k_self1<<<dim3(NG, 2), 32>>>(anchor_t);
  k_edge_add1<<<SP, 256>>>(edge_src, edge_dst, anchor_t);
  k_gemm_list<<<GL, 256>>>(list1, cnt, 0, z1, dz, Wg, bg, h1, dh1);
  k_mark_edges2<<<(E + 255) / 256, 256>>>(edge_src, edge_dst);
  k_compact2<<<(N + 255) / 256, 256>>>();
  k_zero_rows<<<SP, 256>>>(1);
  k_self2<<<SP, 256>>>();
  k_edge_add2<<<SP, 256>>>(edge_src, edge_dst);
  k_gemm_list<<<GL, 256>>>(list2, cnt, 4, z2, dz, Wg + D * D, bg + D, h2, dh2);
  k_gemm_list<<<GL, 256>>>(list2, cnt, 4, h2, dh2, Wn, bn, hn, dhn);
  k_pool_delta<<<dim3(256, 2), 128>>>(batch);

  // ---- head ----
  k_out<<<NG, 32>>>(Wp, bp, out);
}